// round 1
// baseline (speedup 1.0000x reference)
#include <cuda_runtime.h>
#include <math.h>

// Problem constants (fixed by the dataset)
#define MAXN 50000
#define MAXE 800000

// Scratch (allocation-free rule: __device__ globals)
__device__ float g_P[MAXN * 64];     // s @ ng_w1[0:64]
__device__ float g_sagg[MAXN * 64];  // segment_sum(msg)
__device__ float g_vagg[MAXN * 3];   // segment_sum(v_msg)

__device__ __forceinline__ float siluf(float x) { return x / (1.0f + __expf(-x)); }

// ---------------------------------------------------------------- zero scratch
__global__ void zero_kernel(int n64, int n3) {
    int i = blockIdx.x * blockDim.x + threadIdx.x;
    int stride = gridDim.x * blockDim.x;
    for (int k = i; k < n64; k += stride) g_sagg[k] = 0.0f;
    for (int k = i; k < n3; k += stride) g_vagg[k] = 0.0f;
}

// ---------------------------------------------------------------- P = s @ ng_w1[0:64,:]
__global__ __launch_bounds__(256) void pre_kernel(const float* __restrict__ s,
                                                  const float* __restrict__ ngw1, int N) {
    __shared__ float wt[64][68];   // transposed: wt[f][k] = ngw1[k*64+f]
    __shared__ float xs[4][68];
    const int tid = threadIdx.x;
    for (int idx = tid; idx < 64 * 64; idx += 256) {
        int k = idx >> 6, f = idx & 63;
        wt[f][k] = ngw1[idx];
    }
    __syncthreads();
    const int slot = tid >> 6, f = tid & 63;
    for (int n0 = blockIdx.x * 4; n0 < N; n0 += gridDim.x * 4) {
        int n = n0 + slot;
        xs[slot][f] = (n < N) ? s[n * 64 + f] : 0.0f;
        __syncthreads();
        float acc = 0.0f;
#pragma unroll 4
        for (int k = 0; k < 64; k += 4) {
            float4 w = *(const float4*)&wt[f][k];
            float4 x = *(const float4*)&xs[slot][k];
            acc += w.x * x.x + w.y * x.y + w.z * x.z + w.w * x.w;
        }
        if (n < N) g_P[n * 64 + f] = acc;
        __syncthreads();
    }
}

// ---------------------------------------------------------------- fused edge kernel
// Block = 512 threads = 8 rows x 64 lanes (feature f). Each row owns 3 edges per tile
// (24 edges/tile), so every weight LDS.128 is reused across 3 edges.
// All weights live in SMEM, transposed with row strides == 4 (mod 32) floats so that
// per-lane float4 reads are bank-conflict-free.
struct __align__(16) EdgeSmem {
    float ngw2t[64][68];    // ng_w2 transposed  [f][k]
    float egw1t[64][68];    // eg_w1 transposed  (k: 0..64)
    float egw2t[64][68];
    float mgw1t[128][196];  // mg_w1 transposed  (k: 0..191)
    float mgw2t[64][132];   // mg_w2 transposed  (k: 0..127)
    float w65[64];          // ng_w1 row 64 (res coefficient)
    float pew[64];
    float b_ng1[64], b_ng2[64], b_eg1[64], b_eg2[64];
    float b_mg1[128], b_mg2[64];
    float X[24][192];       // concat buffer [nf_i | nf_j | ef], later msg in [0..63]
    float SC[24][136];      // staging: ea65 -> h1_e -> (h1_i|h1_j) -> hm(128)
    float resI[24], resJ[24];
    float evu_s[24][3];
    float coeff[24];
    int eRow[24], eCol[24];
    int validf[24];
};

__global__ __launch_bounds__(512) void edge_kernel(
    const float* __restrict__ v, const int* __restrict__ ei,
    const float* __restrict__ ea, const float* __restrict__ evu,
    const float* __restrict__ ngw1, const float* __restrict__ ngb1,
    const float* __restrict__ ngw2, const float* __restrict__ ngb2,
    const float* __restrict__ egw1, const float* __restrict__ egb1,
    const float* __restrict__ egw2, const float* __restrict__ egb2,
    const float* __restrict__ mgw1, const float* __restrict__ mgb1,
    const float* __restrict__ mgw2, const float* __restrict__ mgb2,
    const float* __restrict__ pew_g, const float* __restrict__ peb,
    int N, int E) {
    extern __shared__ char smem_raw[];
    EdgeSmem& sm = *reinterpret_cast<EdgeSmem*>(smem_raw);
    const int tid = threadIdx.x;

    // ---- one-time weight staging (transposed) ----
    for (int idx = tid; idx < 64 * 64; idx += 512) {
        int k = idx >> 6, f = idx & 63;
        sm.ngw2t[f][k] = ngw2[idx];
        sm.egw2t[f][k] = egw2[idx];
    }
    for (int idx = tid; idx < 65 * 64; idx += 512) {
        int k = idx >> 6, f = idx & 63;
        sm.egw1t[f][k] = egw1[idx];
    }
    for (int idx = tid; idx < 192 * 128; idx += 512) {
        int k = idx >> 7, f = idx & 127;
        sm.mgw1t[f][k] = mgw1[idx];
    }
    for (int idx = tid; idx < 128 * 64; idx += 512) {
        int k = idx >> 6, f = idx & 63;
        sm.mgw2t[f][k] = mgw2[idx];
    }
    if (tid < 64) {
        sm.w65[tid] = ngw1[64 * 64 + tid];
        sm.pew[tid] = pew_g[tid];
        sm.b_ng1[tid] = ngb1[tid];
        sm.b_ng2[tid] = ngb2[tid];
        sm.b_eg1[tid] = egb1[tid];
        sm.b_eg2[tid] = egb2[tid];
        sm.b_mg2[tid] = mgb2[tid];
    }
    if (tid >= 64 && tid < 192) sm.b_mg1[tid - 64] = mgb1[tid - 64];
    __syncthreads();

    const int f = tid & 63;
    const int rowi = tid >> 6;  // 0..7
    const int i0 = rowi * 3;
    const float pb0 = peb[0];

    for (int base = blockIdx.x * 24; base < E; base += gridDim.x * 24) {
        // ---- S0: gather scalars + edge_attr staging ----
        if (tid < 24) {
            int e = base + tid;
            int ok = (e < E);
            sm.validf[tid] = ok;
            if (ok) {
                int r = ei[e], c = ei[E + e];
                sm.eRow[tid] = r;
                sm.eCol[tid] = c;
                float vx = v[r * 3 + 0], vy = v[r * 3 + 1], vz = v[r * 3 + 2];
                float wx = v[c * 3 + 0], wy = v[c * 3 + 1], wz = v[c * 3 + 2];
                float ux = evu[e * 3 + 0], uy = evu[e * 3 + 1], uz = evu[e * 3 + 2];
                sm.evu_s[tid][0] = ux; sm.evu_s[tid][1] = uy; sm.evu_s[tid][2] = uz;
                sm.resI[tid] = 1.0f - (vx * ux + vy * uy + vz * uz);
                sm.resJ[tid] = 1.0f + (wx * ux + wy * uy + wz * uz);
                float cx = vy * wz - vz * wy;
                float cy = vz * wx - vx * wz;
                float cz = vx * wy - vy * wx;
                sm.SC[tid][64] = sqrtf(cx * cx + cy * cy + cz * cz);  // cross_mag
            } else {
                sm.eRow[tid] = 0; sm.eCol[tid] = 0;
                sm.resI[tid] = 0.0f; sm.resJ[tid] = 0.0f;
                sm.SC[tid][64] = 0.0f;
                sm.evu_s[tid][0] = sm.evu_s[tid][1] = sm.evu_s[tid][2] = 0.0f;
            }
        }
        for (int idx = tid; idx < 24 * 64; idx += 512) {
            int i = idx >> 6, k = idx & 63;
            int e = base + i;
            sm.SC[i][k] = (e < E) ? ea[e * 64 + k] : 0.0f;
        }
        __syncthreads();

        // ---- S1: edge MLP layer1 : h1_e = silu(ea65 @ eg_w1 + b) ----
        float a0 = sm.b_eg1[f], a1 = a0, a2 = a0;
#pragma unroll 4
        for (int k = 0; k < 64; k += 4) {
            float4 w = *(const float4*)&sm.egw1t[f][k];
            float4 xa = *(const float4*)&sm.SC[i0 + 0][k];
            float4 xb = *(const float4*)&sm.SC[i0 + 1][k];
            float4 xc = *(const float4*)&sm.SC[i0 + 2][k];
            a0 += w.x * xa.x + w.y * xa.y + w.z * xa.z + w.w * xa.w;
            a1 += w.x * xb.x + w.y * xb.y + w.z * xb.z + w.w * xb.w;
            a2 += w.x * xc.x + w.y * xc.y + w.z * xc.z + w.w * xc.w;
        }
        {
            float w64v = sm.egw1t[f][64];
            a0 += sm.SC[i0 + 0][64] * w64v;
            a1 += sm.SC[i0 + 1][64] * w64v;
            a2 += sm.SC[i0 + 2][64] * w64v;
        }
        __syncthreads();
        sm.SC[i0 + 0][f] = siluf(a0);
        sm.SC[i0 + 1][f] = siluf(a1);
        sm.SC[i0 + 2][f] = siluf(a2);
        __syncthreads();

        // ---- S2: edge MLP layer2 -> ef into X[.][128+f] ----
        a0 = sm.b_eg2[f]; a1 = a0; a2 = a0;
#pragma unroll 4
        for (int k = 0; k < 64; k += 4) {
            float4 w = *(const float4*)&sm.egw2t[f][k];
            float4 xa = *(const float4*)&sm.SC[i0 + 0][k];
            float4 xb = *(const float4*)&sm.SC[i0 + 1][k];
            float4 xc = *(const float4*)&sm.SC[i0 + 2][k];
            a0 += w.x * xa.x + w.y * xa.y + w.z * xa.z + w.w * xa.w;
            a1 += w.x * xb.x + w.y * xb.y + w.z * xb.z + w.w * xb.w;
            a2 += w.x * xc.x + w.y * xc.y + w.z * xc.z + w.w * xc.w;
        }
        sm.X[i0 + 0][128 + f] = a0;
        sm.X[i0 + 1][128 + f] = a1;
        sm.X[i0 + 2][128 + f] = a2;
        __syncthreads();

        // ---- S3: node MLP layer1 via precomputed P ----
#pragma unroll
        for (int j = 0; j < 3; j++) {
            int i = i0 + j;
            float pi = 0.0f, pj = 0.0f;
            if (sm.validf[i]) {
                pi = g_P[sm.eRow[i] * 64 + f];
                pj = g_P[sm.eCol[i] * 64 + f];
            }
            float w65v = sm.w65[f], b1v = sm.b_ng1[f];
            sm.SC[i][f]      = siluf(pi + sm.resI[i] * w65v + b1v);
            sm.SC[i][64 + f] = siluf(pj + sm.resJ[i] * w65v + b1v);
        }
        __syncthreads();

        // ---- S4: node MLP layer2 -> nf_i in X[.][f], nf_j in X[.][64+f] ----
        {
            float bI = sm.b_ng2[f];
            float aI0 = bI, aI1 = bI, aI2 = bI;
            float aJ0 = bI, aJ1 = bI, aJ2 = bI;
#pragma unroll 4
            for (int k = 0; k < 64; k += 4) {
                float4 w = *(const float4*)&sm.ngw2t[f][k];
                float4 xi0 = *(const float4*)&sm.SC[i0 + 0][k];
                float4 xj0 = *(const float4*)&sm.SC[i0 + 0][64 + k];
                float4 xi1 = *(const float4*)&sm.SC[i0 + 1][k];
                float4 xj1 = *(const float4*)&sm.SC[i0 + 1][64 + k];
                float4 xi2 = *(const float4*)&sm.SC[i0 + 2][k];
                float4 xj2 = *(const float4*)&sm.SC[i0 + 2][64 + k];
                aI0 += w.x * xi0.x + w.y * xi0.y + w.z * xi0.z + w.w * xi0.w;
                aJ0 += w.x * xj0.x + w.y * xj0.y + w.z * xj0.z + w.w * xj0.w;
                aI1 += w.x * xi1.x + w.y * xi1.y + w.z * xi1.z + w.w * xi1.w;
                aJ1 += w.x * xj1.x + w.y * xj1.y + w.z * xj1.z + w.w * xj1.w;
                aI2 += w.x * xi2.x + w.y * xi2.y + w.z * xi2.z + w.w * xi2.w;
                aJ2 += w.x * xj2.x + w.y * xj2.y + w.z * xj2.z + w.w * xj2.w;
            }
            sm.X[i0 + 0][f] = aI0; sm.X[i0 + 0][64 + f] = aJ0;
            sm.X[i0 + 1][f] = aI1; sm.X[i0 + 1][64 + f] = aJ1;
            sm.X[i0 + 2][f] = aI2; sm.X[i0 + 2][64 + f] = aJ2;
        }
        __syncthreads();

        // ---- S5: msg layer1 (192 -> 128): outputs f and f+64 ----
        {
            float hA0 = sm.b_mg1[f], hA1 = hA0, hA2 = hA0;
            float hB0 = sm.b_mg1[64 + f], hB1 = hB0, hB2 = hB0;
#pragma unroll 4
            for (int k = 0; k < 192; k += 4) {
                float4 wa = *(const float4*)&sm.mgw1t[f][k];
                float4 wb = *(const float4*)&sm.mgw1t[64 + f][k];
                float4 x0 = *(const float4*)&sm.X[i0 + 0][k];
                float4 x1 = *(const float4*)&sm.X[i0 + 1][k];
                float4 x2 = *(const float4*)&sm.X[i0 + 2][k];
                hA0 += wa.x * x0.x + wa.y * x0.y + wa.z * x0.z + wa.w * x0.w;
                hB0 += wb.x * x0.x + wb.y * x0.y + wb.z * x0.z + wb.w * x0.w;
                hA1 += wa.x * x1.x + wa.y * x1.y + wa.z * x1.z + wa.w * x1.w;
                hB1 += wb.x * x1.x + wb.y * x1.y + wb.z * x1.z + wb.w * x1.w;
                hA2 += wa.x * x2.x + wa.y * x2.y + wa.z * x2.z + wa.w * x2.w;
                hB2 += wb.x * x2.x + wb.y * x2.y + wb.z * x2.z + wb.w * x2.w;
            }
            sm.SC[i0 + 0][f] = siluf(hA0); sm.SC[i0 + 0][64 + f] = siluf(hB0);
            sm.SC[i0 + 1][f] = siluf(hA1); sm.SC[i0 + 1][64 + f] = siluf(hB1);
            sm.SC[i0 + 2][f] = siluf(hA2); sm.SC[i0 + 2][64 + f] = siluf(hB2);
        }
        __syncthreads();

        // ---- S6: msg layer2 (128 -> 64) + s_agg atomics ----
        {
            float m0 = sm.b_mg2[f], m1 = m0, m2 = m0;
#pragma unroll 4
            for (int k = 0; k < 128; k += 4) {
                float4 w = *(const float4*)&sm.mgw2t[f][k];
                float4 x0 = *(const float4*)&sm.SC[i0 + 0][k];
                float4 x1 = *(const float4*)&sm.SC[i0 + 1][k];
                float4 x2 = *(const float4*)&sm.SC[i0 + 2][k];
                m0 += w.x * x0.x + w.y * x0.y + w.z * x0.z + w.w * x0.w;
                m1 += w.x * x1.x + w.y * x1.y + w.z * x1.z + w.w * x1.w;
                m2 += w.x * x2.x + w.y * x2.y + w.z * x2.z + w.w * x2.w;
            }
            sm.X[i0 + 0][f] = m0;
            sm.X[i0 + 1][f] = m1;
            sm.X[i0 + 2][f] = m2;
            if (sm.validf[i0 + 0]) atomicAdd(&g_sagg[sm.eRow[i0 + 0] * 64 + f], m0);
            if (sm.validf[i0 + 1]) atomicAdd(&g_sagg[sm.eRow[i0 + 1] * 64 + f], m1);
            if (sm.validf[i0 + 2]) atomicAdd(&g_sagg[sm.eRow[i0 + 2] * 64 + f], m2);
        }
        __syncthreads();

        // ---- S7: coeff = msg @ pe_w + pe_b ; v_agg atomics ----
        if (tid < 24 && sm.validf[tid]) {
            float c = pb0;
#pragma unroll 4
            for (int k = 0; k < 64; k += 4) {
                float4 p = *(const float4*)&sm.pew[k];
                float4 m = *(const float4*)&sm.X[tid][k];
                c += p.x * m.x + p.y * m.y + p.z * m.z + p.w * m.w;
            }
            sm.coeff[tid] = c;
        }
        __syncthreads();
        if (tid < 72) {
            int i = tid / 3, cc = tid % 3;
            if (sm.validf[i])
                atomicAdd(&g_vagg[sm.eRow[i] * 3 + cc], sm.evu_s[i][cc] * sm.coeff[i]);
        }
        __syncthreads();  // protects X/SC/scalar reuse next iteration
    }
}

// ---------------------------------------------------------------- node finalize
__global__ __launch_bounds__(256) void post_kernel(
    const float* __restrict__ s, const float* __restrict__ v,
    const float* __restrict__ upw, const float* __restrict__ upb,
    const float* __restrict__ lng, const float* __restrict__ lnb,
    float* __restrict__ outs, float* __restrict__ outv, int N) {
    __shared__ float wt[64][68];  // up_w transposed
    __shared__ float xs[4][68];   // silu(s_agg)
    __shared__ float sn[4][68];   // s_new (for layernorm reduce)
    const int tid = threadIdx.x;
    for (int idx = tid; idx < 64 * 64; idx += 256) {
        int k = idx >> 6, f = idx & 63;
        wt[f][k] = upw[idx];
    }
    __syncthreads();
    const int slot = tid >> 6, f = tid & 63;
    for (int n0 = blockIdx.x * 4; n0 < N; n0 += gridDim.x * 4) {
        int n = n0 + slot;
        bool ok = (n < N);
        xs[slot][f] = ok ? siluf(g_sagg[n * 64 + f]) : 0.0f;
        __syncthreads();
        float acc = upb[f];
#pragma unroll 4
        for (int k = 0; k < 64; k += 4) {
            float4 w = *(const float4*)&wt[f][k];
            float4 x = *(const float4*)&xs[slot][k];
            acc += w.x * x.x + w.y * x.y + w.z * x.z + w.w * x.w;
        }
        float snew = ok ? (s[n * 64 + f] + acc) : 0.0f;
        sn[slot][f] = snew;
        __syncthreads();
        float sum = 0.0f, sq = 0.0f;
#pragma unroll 4
        for (int k = 0; k < 64; k += 4) {
            float4 t = *(const float4*)&sn[slot][k];
            sum += t.x + t.y + t.z + t.w;
            sq += t.x * t.x + t.y * t.y + t.z * t.z + t.w * t.w;
        }
        float mu = sum * (1.0f / 64.0f);
        float var = sq * (1.0f / 64.0f) - mu * mu;
        if (ok) {
            outs[n * 64 + f] = (snew - mu) * rsqrtf(var + 1e-5f) * lng[f] + lnb[f];
            if (f < 3) {
                float v0 = v[n * 3 + 0] + g_vagg[n * 3 + 0];
                float v1 = v[n * 3 + 1] + g_vagg[n * 3 + 1];
                float v2 = v[n * 3 + 2] + g_vagg[n * 3 + 2];
                float nrm = sqrtf(v0 * v0 + v1 * v1 + v2 * v2);
                float inv = 1.0f / fmaxf(nrm, 1e-6f);
                float val = (f == 0) ? v0 : (f == 1) ? v1 : v2;
                outv[n * 3 + f] = val * inv;
            }
        }
        __syncthreads();
    }
}

// ---------------------------------------------------------------- launch
extern "C" void kernel_launch(void* const* d_in, const int* in_sizes, int n_in,
                              void* d_out, int out_size) {
    const float* s    = (const float*)d_in[0];
    const float* v    = (const float*)d_in[1];
    const int*   ei   = (const int*)d_in[2];
    const float* ea   = (const float*)d_in[3];
    const float* evu  = (const float*)d_in[4];
    const float* ngw1 = (const float*)d_in[5];
    const float* ngb1 = (const float*)d_in[6];
    const float* ngw2 = (const float*)d_in[7];
    const float* ngb2 = (const float*)d_in[8];
    const float* egw1 = (const float*)d_in[9];
    const float* egb1 = (const float*)d_in[10];
    const float* egw2 = (const float*)d_in[11];
    const float* egb2 = (const float*)d_in[12];
    const float* mgw1 = (const float*)d_in[13];
    const float* mgb1 = (const float*)d_in[14];
    const float* mgw2 = (const float*)d_in[15];
    const float* mgb2 = (const float*)d_in[16];
    const float* pew  = (const float*)d_in[17];
    const float* peb  = (const float*)d_in[18];
    const float* upw  = (const float*)d_in[19];
    const float* upb  = (const float*)d_in[20];
    const float* lng  = (const float*)d_in[21];
    const float* lnb  = (const float*)d_in[22];

    const int N = in_sizes[0] / 64;
    const int E = in_sizes[2] / 2;

    float* outs = (float*)d_out;
    float* outv = outs + (size_t)N * 64;

    int nsm = 148;
    cudaDeviceGetAttribute(&nsm, cudaDevAttrMultiProcessorCount, 0);

    zero_kernel<<<512, 256>>>(N * 64, N * 3);
    pre_kernel<<<1184, 256>>>(s, ngw1, N);

    cudaFuncSetAttribute(edge_kernel, cudaFuncAttributeMaxDynamicSharedMemorySize,
                         (int)sizeof(EdgeSmem));
    edge_kernel<<<nsm, 512, sizeof(EdgeSmem)>>>(
        v, ei, ea, evu, ngw1, ngb1, ngw2, ngb2, egw1, egb1, egw2, egb2,
        mgw1, mgb1, mgw2, mgb2, pew, peb, N, E);

    post_kernel<<<1184, 256>>>(s, v, upw, upb, lng, lnb, outs, outv, N);
}

// round 2
// speedup vs baseline: 1.8269x; 1.8269x over previous
#include <cuda_runtime.h>
#include <math.h>

#define MAXN 50000
#define MAXE 800000

// ---- device scratch (allocation-free rule) ----
__device__ float g_P[MAXN * 64];      // s @ ng_w1[0:64]
__device__ float g_z[MAXN * 128];     // segsum(silu(hm))
__device__ float g_vagg[MAXN * 3];
__device__ float g_deg[MAXN];
__device__ float g_Wpt[128 * 192];    // fused W' transposed: [o][r]
__device__ float g_b1p[128];          // fused bias into hm
__device__ float g_q[128];            // mg_w2 @ pe_w
__device__ float g_qb[1];             // b_mg2 @ pe_w + pe_b

__device__ __forceinline__ float siluf(float x) { return x / (1.0f + __expf(-x)); }

__device__ __forceinline__ void redv4(float* p, float4 v) {
    asm volatile("red.global.add.v4.f32 [%0], {%1,%2,%3,%4};"
                 :: "l"(p), "f"(v.x), "f"(v.y), "f"(v.z), "f"(v.w) : "memory");
}
__device__ __forceinline__ void reds(float* p, float v) {
    asm volatile("red.global.add.f32 [%0], %1;" :: "l"(p), "f"(v) : "memory");
}

// ---------------------------------------------------------------- zero scratch
__global__ void zero_kernel(int n128, int n3, int n1) {
    int i = blockIdx.x * blockDim.x + threadIdx.x;
    int stride = gridDim.x * blockDim.x;
    for (int k = i; k < n128; k += stride) g_z[k] = 0.0f;
    for (int k = i; k < n3; k += stride) g_vagg[k] = 0.0f;
    for (int k = i; k < n1; k += stride) g_deg[k] = 0.0f;
}

// ---------------------------------------------------------------- P = s @ ng_w1[0:64,:]
__global__ __launch_bounds__(256) void pre_kernel(const float* __restrict__ s,
                                                  const float* __restrict__ ngw1, int N) {
    __shared__ float wt[64][68];
    __shared__ float xs[4][68];
    const int tid = threadIdx.x;
    for (int idx = tid; idx < 64 * 64; idx += 256) {
        int k = idx >> 6, f = idx & 63;
        wt[f][k] = ngw1[idx];
    }
    __syncthreads();
    const int slot = tid >> 6, f = tid & 63;
    for (int n0 = blockIdx.x * 4; n0 < N; n0 += gridDim.x * 4) {
        int n = n0 + slot;
        xs[slot][f] = (n < N) ? s[n * 64 + f] : 0.0f;
        __syncthreads();
        float acc = 0.0f;
#pragma unroll 4
        for (int k = 0; k < 64; k += 4) {
            float4 w = *(const float4*)&wt[f][k];
            float4 x = *(const float4*)&xs[slot][k];
            acc += w.x * x.x + w.y * x.y + w.z * x.z + w.w * x.w;
        }
        if (n < N) g_P[n * 64 + f] = acc;
        __syncthreads();
    }
}

// ---------------------------------------------------------------- fold weights
// W'[r][o]: r<64: ng_w2@mg_w1[0:64]; r<128: ng_w2@mg_w1[64:128]; else eg_w2@mg_w1[128:192]
__global__ void preW_kernel(const float* __restrict__ ngw2, const float* __restrict__ ngb2,
                            const float* __restrict__ egw2, const float* __restrict__ egb2,
                            const float* __restrict__ mgw1, const float* __restrict__ mgb1,
                            const float* __restrict__ mgw2, const float* __restrict__ mgb2,
                            const float* __restrict__ pew, const float* __restrict__ peb) {
    int idx = blockIdx.x * blockDim.x + threadIdx.x;
    int stride = gridDim.x * blockDim.x;
    for (int t = idx; t < 128 * 192 + 128 + 128 + 1; t += stride) {
        if (t < 128 * 192) {
            int o = t / 192, r = t % 192;
            int seg = r >> 6, rr = r & 63, koff = seg * 64;
            const float* src = (seg < 2) ? ngw2 : egw2;
            float val = 0.0f;
            for (int k = 0; k < 64; k++)
                val += src[rr * 64 + k] * mgw1[(koff + k) * 128 + o];
            g_Wpt[o * 192 + r] = val;
        } else if (t < 128 * 192 + 128) {
            int o = t - 128 * 192;
            float val = mgb1[o];
            for (int k = 0; k < 64; k++) {
                val += ngb2[k] * (mgw1[k * 128 + o] + mgw1[(64 + k) * 128 + o]);
                val += egb2[k] * mgw1[(128 + k) * 128 + o];
            }
            g_b1p[o] = val;
        } else if (t < 128 * 192 + 256) {
            int o = t - 128 * 192 - 128;
            float val = 0.0f;
            for (int j = 0; j < 64; j++) val += mgw2[o * 64 + j] * pew[j];
            g_q[o] = val;
        } else {
            float val = peb[0];
            for (int j = 0; j < 64; j++) val += mgb2[j] * pew[j];
            g_qb[0] = val;
        }
    }
}

// ---------------------------------------------------------------- fused edge kernel
// 768 threads = 12 rows x 64 lanes; 3 edges per row -> 36 edges/tile; 4 barriers/tile.
struct __align__(16) EdgeSmem {
    float egw1t[64][68];    // eg_w1 transposed [f][k], k=0..64
    float wpt[128][196];    // fused W' transposed [o][r], r=0..191
    float X[36][192];       // [h_i | h_j | h_e]
    float HM[36][128];      // stage ea(+cross at 64) -> later g = silu(hm)
    float w65[64], bng1[64], beg1[64];
    float b1p[128], q[128];
    float resI[36], resJ[36];
    float evu_s[36][3];
    float pc[12][3][2];     // coeff partials per (row, edge, warp-half)
    int eRow[36], eCol[36], valid[36];
    float qb;
};

__global__ __launch_bounds__(768) void edge_kernel(
    const float* __restrict__ v, const int* __restrict__ ei,
    const float* __restrict__ ea, const float* __restrict__ evu,
    const float* __restrict__ ngw1, const float* __restrict__ ngb1,
    const float* __restrict__ egw1, const float* __restrict__ egb1,
    int N, int E) {
    extern __shared__ char smem_raw[];
    EdgeSmem& sm = *reinterpret_cast<EdgeSmem*>(smem_raw);
    const int tid = threadIdx.x;

    // ---- one-time staging ----
    for (int idx = tid; idx < 65 * 64; idx += 768) {
        int k = idx >> 6, f = idx & 63;
        sm.egw1t[f][k] = egw1[idx];
    }
    for (int idx = tid; idx < 128 * 192; idx += 768) {
        int o = idx / 192, r = idx % 192;
        sm.wpt[o][r] = g_Wpt[idx];
    }
    if (tid < 64) {
        sm.w65[tid] = ngw1[64 * 64 + tid];
        sm.bng1[tid] = ngb1[tid];
        sm.beg1[tid] = egb1[tid];
    } else if (tid < 192) {
        sm.b1p[tid - 64] = g_b1p[tid - 64];
    } else if (tid < 320) {
        sm.q[tid - 192] = g_q[tid - 192];
    } else if (tid == 320) {
        sm.qb = g_qb[0];
    }
    __syncthreads();

    const int f = tid & 63;
    const int row = tid >> 6;   // 0..11
    const int i0 = row * 3;

    for (int base = blockIdx.x * 36; base < E; base += gridDim.x * 36) {
        // ---- S0: scalars + ea staging ----
        if (tid < 36) {
            int e = base + tid;
            int ok = (e < E);
            sm.valid[tid] = ok;
            if (ok) {
                int r = ei[e], c = ei[E + e];
                sm.eRow[tid] = r;
                sm.eCol[tid] = c;
                float vx = v[r * 3 + 0], vy = v[r * 3 + 1], vz = v[r * 3 + 2];
                float wx = v[c * 3 + 0], wy = v[c * 3 + 1], wz = v[c * 3 + 2];
                float ux = evu[e * 3 + 0], uy = evu[e * 3 + 1], uz = evu[e * 3 + 2];
                sm.evu_s[tid][0] = ux; sm.evu_s[tid][1] = uy; sm.evu_s[tid][2] = uz;
                sm.resI[tid] = 1.0f - (vx * ux + vy * uy + vz * uz);
                sm.resJ[tid] = 1.0f + (wx * ux + wy * uy + wz * uz);
                float cx = vy * wz - vz * wy;
                float cy = vz * wx - vx * wz;
                float cz = vx * wy - vy * wx;
                sm.HM[tid][64] = sqrtf(cx * cx + cy * cy + cz * cz);
            } else {
                sm.eRow[tid] = 0; sm.eCol[tid] = 0;
                sm.resI[tid] = 0.0f; sm.resJ[tid] = 0.0f;
                sm.HM[tid][64] = 0.0f;
                sm.evu_s[tid][0] = sm.evu_s[tid][1] = sm.evu_s[tid][2] = 0.0f;
            }
        }
        if (tid < 576) {  // 36 edges x 16 float4
            int i = tid >> 4, qd = tid & 15;
            int e = base + i;
            float4 val = make_float4(0.f, 0.f, 0.f, 0.f);
            if (e < E) val = *(const float4*)&ea[e * 64 + qd * 4];
            *(float4*)&sm.HM[i][qd * 4] = val;
        }
        __syncthreads();

        // ---- S1: h_e = silu([ea|cross]@eg_w1 + b) ; h_i,h_j via P ----
        float pi[3], pj[3];
#pragma unroll
        for (int j = 0; j < 3; j++) {
            int i = i0 + j;
            pi[j] = 0.0f; pj[j] = 0.0f;
            if (sm.valid[i]) {
                pi[j] = g_P[sm.eRow[i] * 64 + f];
                pj[j] = g_P[sm.eCol[i] * 64 + f];
            }
        }
        {
            float a0 = sm.beg1[f], a1 = a0, a2 = a0;
#pragma unroll 4
            for (int k = 0; k < 64; k += 4) {
                float4 w = *(const float4*)&sm.egw1t[f][k];
                float4 xa = *(const float4*)&sm.HM[i0 + 0][k];
                float4 xb = *(const float4*)&sm.HM[i0 + 1][k];
                float4 xc = *(const float4*)&sm.HM[i0 + 2][k];
                a0 += w.x * xa.x + w.y * xa.y + w.z * xa.z + w.w * xa.w;
                a1 += w.x * xb.x + w.y * xb.y + w.z * xb.z + w.w * xb.w;
                a2 += w.x * xc.x + w.y * xc.y + w.z * xc.z + w.w * xc.w;
            }
            float w64v = sm.egw1t[f][64];
            a0 += sm.HM[i0 + 0][64] * w64v;
            a1 += sm.HM[i0 + 1][64] * w64v;
            a2 += sm.HM[i0 + 2][64] * w64v;
            sm.X[i0 + 0][128 + f] = siluf(a0);
            sm.X[i0 + 1][128 + f] = siluf(a1);
            sm.X[i0 + 2][128 + f] = siluf(a2);
        }
        {
            float w65v = sm.w65[f], b1v = sm.bng1[f];
#pragma unroll
            for (int j = 0; j < 3; j++) {
                int i = i0 + j;
                sm.X[i][f]      = siluf(pi[j] + sm.resI[i] * w65v + b1v);
                sm.X[i][64 + f] = siluf(pj[j] + sm.resJ[i] * w65v + b1v);
            }
        }
        __syncthreads();

        // ---- S2: hm = X @ W' + b1p ; g = silu(hm) ; coeff partials ----
        float gA0, gA1, gA2, gB0, gB1, gB2;
        {
            float hA0 = sm.b1p[f], hA1 = hA0, hA2 = hA0;
            float hB0 = sm.b1p[64 + f], hB1 = hB0, hB2 = hB0;
#pragma unroll 4
            for (int k = 0; k < 192; k += 4) {
                float4 wa = *(const float4*)&sm.wpt[f][k];
                float4 wb = *(const float4*)&sm.wpt[64 + f][k];
                float4 x0 = *(const float4*)&sm.X[i0 + 0][k];
                float4 x1 = *(const float4*)&sm.X[i0 + 1][k];
                float4 x2 = *(const float4*)&sm.X[i0 + 2][k];
                hA0 += wa.x * x0.x + wa.y * x0.y + wa.z * x0.z + wa.w * x0.w;
                hB0 += wb.x * x0.x + wb.y * x0.y + wb.z * x0.z + wb.w * x0.w;
                hA1 += wa.x * x1.x + wa.y * x1.y + wa.z * x1.z + wa.w * x1.w;
                hB1 += wb.x * x1.x + wb.y * x1.y + wb.z * x1.z + wb.w * x1.w;
                hA2 += wa.x * x2.x + wa.y * x2.y + wa.z * x2.z + wa.w * x2.w;
                hB2 += wb.x * x2.x + wb.y * x2.y + wb.z * x2.z + wb.w * x2.w;
            }
            gA0 = siluf(hA0); gA1 = siluf(hA1); gA2 = siluf(hA2);
            gB0 = siluf(hB0); gB1 = siluf(hB1); gB2 = siluf(hB2);
            sm.HM[i0 + 0][f] = gA0; sm.HM[i0 + 0][64 + f] = gB0;
            sm.HM[i0 + 1][f] = gA1; sm.HM[i0 + 1][64 + f] = gB1;
            sm.HM[i0 + 2][f] = gA2; sm.HM[i0 + 2][64 + f] = gB2;
        }
        {
            float qf = sm.q[f], qf64 = sm.q[64 + f];
            float p0 = gA0 * qf + gB0 * qf64;
            float p1 = gA1 * qf + gB1 * qf64;
            float p2 = gA2 * qf + gB2 * qf64;
#pragma unroll
            for (int off = 16; off > 0; off >>= 1) {
                p0 += __shfl_down_sync(0xffffffffu, p0, off);
                p1 += __shfl_down_sync(0xffffffffu, p1, off);
                p2 += __shfl_down_sync(0xffffffffu, p2, off);
            }
            if ((tid & 31) == 0) {
                int half = (tid >> 5) & 1;
                sm.pc[row][0][half] = p0;
                sm.pc[row][1][half] = p1;
                sm.pc[row][2][half] = p2;
            }
        }
        __syncthreads();

        // ---- S3: atomics ----
        if (tid < 36 && sm.valid[tid]) {
            int rr = tid / 3, j = tid % 3;
            float c = sm.qb + sm.pc[rr][j][0] + sm.pc[rr][j][1];
            int dst = sm.eRow[tid];
            reds(&g_vagg[dst * 3 + 0], sm.evu_s[tid][0] * c);
            reds(&g_vagg[dst * 3 + 1], sm.evu_s[tid][1] * c);
            reds(&g_vagg[dst * 3 + 2], sm.evu_s[tid][2] * c);
            reds(&g_deg[dst], 1.0f);
        }
        for (int idx = tid; idx < 36 * 32; idx += 768) {
            int i = idx >> 5, qd = idx & 31;
            if (sm.valid[i]) {
                float4 gv = *(const float4*)&sm.HM[i][qd * 4];
                redv4(&g_z[sm.eRow[i] * 128 + qd * 4], gv);
            }
        }
        __syncthreads();
    }
}

// ---------------------------------------------------------------- node finalize
__global__ __launch_bounds__(256) void post_kernel(
    const float* __restrict__ s, const float* __restrict__ v,
    const float* __restrict__ mgw2, const float* __restrict__ mgb2,
    const float* __restrict__ upw, const float* __restrict__ upb,
    const float* __restrict__ lng, const float* __restrict__ lnb,
    float* __restrict__ outs, float* __restrict__ outv, int N) {
    __shared__ float mw2t[64][132];  // [f][k] = mgw2[k*64+f]
    __shared__ float upwt[64][68];
    __shared__ float zs[4][132];
    __shared__ float xs[4][68];
    __shared__ float sn[4][68];
    const int tid = threadIdx.x;
    for (int idx = tid; idx < 128 * 64; idx += 256) {
        int k = idx >> 6, f = idx & 63;
        mw2t[f][k] = mgw2[idx];
    }
    for (int idx = tid; idx < 64 * 64; idx += 256) {
        int k = idx >> 6, f = idx & 63;
        upwt[f][k] = upw[idx];
    }
    __syncthreads();
    const int slot = tid >> 6, f = tid & 63;
    for (int n0 = blockIdx.x * 4; n0 < N; n0 += gridDim.x * 4) {
        int n = n0 + slot;
        bool ok = (n < N);
        zs[slot][f]      = ok ? g_z[n * 128 + f] : 0.0f;
        zs[slot][64 + f] = ok ? g_z[n * 128 + 64 + f] : 0.0f;
        __syncthreads();
        float degv = ok ? g_deg[n] : 0.0f;
        float acc = degv * mgb2[f];
#pragma unroll 4
        for (int k = 0; k < 128; k += 4) {
            float4 w = *(const float4*)&mw2t[f][k];
            float4 x = *(const float4*)&zs[slot][k];
            acc += w.x * x.x + w.y * x.y + w.z * x.z + w.w * x.w;
        }
        xs[slot][f] = siluf(acc);
        __syncthreads();
        float acc2 = upb[f];
#pragma unroll 4
        for (int k = 0; k < 64; k += 4) {
            float4 w = *(const float4*)&upwt[f][k];
            float4 x = *(const float4*)&xs[slot][k];
            acc2 += w.x * x.x + w.y * x.y + w.z * x.z + w.w * x.w;
        }
        float snew = ok ? (s[n * 64 + f] + acc2) : 0.0f;
        sn[slot][f] = snew;
        __syncthreads();
        float sum = 0.0f, sq = 0.0f;
#pragma unroll 4
        for (int k = 0; k < 64; k += 4) {
            float4 t = *(const float4*)&sn[slot][k];
            sum += t.x + t.y + t.z + t.w;
            sq += t.x * t.x + t.y * t.y + t.z * t.z + t.w * t.w;
        }
        float mu = sum * (1.0f / 64.0f);
        float var = sq * (1.0f / 64.0f) - mu * mu;
        if (ok) {
            outs[n * 64 + f] = (snew - mu) * rsqrtf(var + 1e-5f) * lng[f] + lnb[f];
            if (f < 3) {
                float v0 = v[n * 3 + 0] + g_vagg[n * 3 + 0];
                float v1 = v[n * 3 + 1] + g_vagg[n * 3 + 1];
                float v2 = v[n * 3 + 2] + g_vagg[n * 3 + 2];
                float nrm = sqrtf(v0 * v0 + v1 * v1 + v2 * v2);
                float inv = 1.0f / fmaxf(nrm, 1e-6f);
                float val = (f == 0) ? v0 : (f == 1) ? v1 : v2;
                outv[n * 3 + f] = val * inv;
            }
        }
        __syncthreads();
    }
}

// ---------------------------------------------------------------- launch
extern "C" void kernel_launch(void* const* d_in, const int* in_sizes, int n_in,
                              void* d_out, int out_size) {
    const float* s    = (const float*)d_in[0];
    const float* v    = (const float*)d_in[1];
    const int*   ei   = (const int*)d_in[2];
    const float* ea   = (const float*)d_in[3];
    const float* evu  = (const float*)d_in[4];
    const float* ngw1 = (const float*)d_in[5];
    const float* ngb1 = (const float*)d_in[6];
    const float* ngw2 = (const float*)d_in[7];
    const float* ngb2 = (const float*)d_in[8];
    const float* egw1 = (const float*)d_in[9];
    const float* egb1 = (const float*)d_in[10];
    const float* egw2 = (const float*)d_in[11];
    const float* egb2 = (const float*)d_in[12];
    const float* mgw1 = (const float*)d_in[13];
    const float* mgb1 = (const float*)d_in[14];
    const float* mgw2 = (const float*)d_in[15];
    const float* mgb2 = (const float*)d_in[16];
    const float* pew  = (const float*)d_in[17];
    const float* peb  = (const float*)d_in[18];
    const float* upw  = (const float*)d_in[19];
    const float* upb  = (const float*)d_in[20];
    const float* lng  = (const float*)d_in[21];
    const float* lnb  = (const float*)d_in[22];

    const int N = in_sizes[0] / 64;
    const int E = in_sizes[2] / 2;

    float* outs = (float*)d_out;
    float* outv = outs + (size_t)N * 64;

    int nsm = 148;
    cudaDeviceGetAttribute(&nsm, cudaDevAttrMultiProcessorCount, 0);

    zero_kernel<<<512, 256>>>(N * 128, N * 3, N);
    pre_kernel<<<1184, 256>>>(s, ngw1, N);
    preW_kernel<<<128, 256>>>(ngw2, ngb2, egw2, egb2, mgw1, mgb1, mgw2, mgb2, pew, peb);

    cudaFuncSetAttribute(edge_kernel, cudaFuncAttributeMaxDynamicSharedMemorySize,
                         (int)sizeof(EdgeSmem));
    edge_kernel<<<nsm, 768, sizeof(EdgeSmem)>>>(
        v, ei, ea, evu, ngw1, ngb1, egw1, egb1, N, E);

    post_kernel<<<1184, 256>>>(s, v, mgw2, mgb2, upw, upb, lng, lnb, outs, outv, N);
}

// round 3
// speedup vs baseline: 2.4509x; 1.3416x over previous
#include <cuda_runtime.h>
#include <math.h>

#define MAXN 50000
#define MAXE 800000

// ---- device scratch (allocation-free rule) ----
__device__ float g_P[MAXN * 64];      // s @ ng_w1[0:64]
__device__ float g_z[MAXN * 128];     // segsum(silu(hm))
__device__ float g_vagg[MAXN * 3];
__device__ float g_deg[MAXN];
__device__ float g_Wpt[128 * 192];    // fused W' transposed: [o][r]
__device__ float g_b1p[128];          // fused bias into hm
__device__ float g_q[128];            // mg_w2 @ pe_w
__device__ float g_qb[1];             // b_mg2 @ pe_w + pe_b

__device__ __forceinline__ float siluf(float x) { return x / (1.0f + __expf(-x)); }

__device__ __forceinline__ void reds(float* p, float v) {
    asm volatile("red.global.add.f32 [%0], %1;" :: "l"(p), "f"(v) : "memory");
}
__device__ __forceinline__ void barrow(int id) {
    asm volatile("bar.sync %0, 64;" :: "r"(id) : "memory");
}

// ---------------------------------------------------------------- zero scratch
__global__ void zero_kernel(int n128, int n3, int n1) {
    int i = blockIdx.x * blockDim.x + threadIdx.x;
    int stride = gridDim.x * blockDim.x;
    for (int k = i; k < n128; k += stride) g_z[k] = 0.0f;
    for (int k = i; k < n3; k += stride) g_vagg[k] = 0.0f;
    for (int k = i; k < n1; k += stride) g_deg[k] = 0.0f;
}

// ---------------------------------------------------------------- P = s @ ng_w1[0:64,:]
__global__ __launch_bounds__(256) void pre_kernel(const float* __restrict__ s,
                                                  const float* __restrict__ ngw1, int N) {
    __shared__ float wt[64][68];
    __shared__ float xs[4][68];
    const int tid = threadIdx.x;
    for (int idx = tid; idx < 64 * 64; idx += 256) {
        int k = idx >> 6, f = idx & 63;
        wt[f][k] = ngw1[idx];
    }
    __syncthreads();
    const int slot = tid >> 6, f = tid & 63;
    for (int n0 = blockIdx.x * 4; n0 < N; n0 += gridDim.x * 4) {
        int n = n0 + slot;
        xs[slot][f] = (n < N) ? s[n * 64 + f] : 0.0f;
        __syncthreads();
        float acc = 0.0f;
#pragma unroll 4
        for (int k = 0; k < 64; k += 4) {
            float4 w = *(const float4*)&wt[f][k];
            float4 x = *(const float4*)&xs[slot][k];
            acc += w.x * x.x + w.y * x.y + w.z * x.z + w.w * x.w;
        }
        if (n < N) g_P[n * 64 + f] = acc;
        __syncthreads();
    }
}

// ---------------------------------------------------------------- fold weights
__global__ void preW_kernel(const float* __restrict__ ngw2, const float* __restrict__ ngb2,
                            const float* __restrict__ egw2, const float* __restrict__ egb2,
                            const float* __restrict__ mgw1, const float* __restrict__ mgb1,
                            const float* __restrict__ mgw2, const float* __restrict__ mgb2,
                            const float* __restrict__ pew, const float* __restrict__ peb) {
    int idx = blockIdx.x * blockDim.x + threadIdx.x;
    int stride = gridDim.x * blockDim.x;
    for (int t = idx; t < 128 * 192 + 128 + 128 + 1; t += stride) {
        if (t < 128 * 192) {
            int o = t / 192, r = t % 192;
            int seg = r >> 6, rr = r & 63, koff = seg * 64;
            const float* src = (seg < 2) ? ngw2 : egw2;
            float val = 0.0f;
            for (int k = 0; k < 64; k++)
                val += src[rr * 64 + k] * mgw1[(koff + k) * 128 + o];
            g_Wpt[o * 192 + r] = val;
        } else if (t < 128 * 192 + 128) {
            int o = t - 128 * 192;
            float val = mgb1[o];
            for (int k = 0; k < 64; k++) {
                val += ngb2[k] * (mgw1[k * 128 + o] + mgw1[(64 + k) * 128 + o]);
                val += egb2[k] * mgw1[(128 + k) * 128 + o];
            }
            g_b1p[o] = val;
        } else if (t < 128 * 192 + 256) {
            int o = t - 128 * 192 - 128;
            float val = 0.0f;
            for (int j = 0; j < 64; j++) val += mgw2[o * 64 + j] * pew[j];
            g_q[o] = val;
        } else {
            float val = peb[0];
            for (int j = 0; j < 64; j++) val += mgb2[j] * pew[j];
            g_qb[0] = val;
        }
    }
}

// ---------------------------------------------------------------- fused edge kernel
// 768 threads = 12 independent rows x 64 lanes. Each row owns 6 edges per tile.
// Rows sync ONLY among their own 2 warps via named barrier `row` -> no block-wide
// sync in the main loop. Weights read-only in smem.
#define EPR 6  // edges per row

struct __align__(16) EdgeSmem {
    float egw1t[64][68];       // eg_w1 transposed [f][k], k=0..64
    float wpt[128][196];       // fused W' transposed [o][r], r=0..191
    float X[12][EPR][192];     // [h_i | h_j | h_e]
    float EA[12][EPR][68];     // staged edge_attr, cross_mag at [64]
    float w65[64], bng1[64], beg1[64];
    float b1p[128], q[128];
    float resI[12][EPR], resJ[12][EPR];
    float evu_s[12][EPR][3];
    int eRow[12][EPR], eCol[12][EPR], valid[12][EPR];
    float qb;
};

__global__ __launch_bounds__(768) void edge_kernel(
    const float* __restrict__ v, const int* __restrict__ ei,
    const float* __restrict__ ea, const float* __restrict__ evu,
    const float* __restrict__ ngw1, const float* __restrict__ ngb1,
    const float* __restrict__ egw1, const float* __restrict__ egb1,
    int N, int E) {
    extern __shared__ char smem_raw[];
    EdgeSmem& sm = *reinterpret_cast<EdgeSmem*>(smem_raw);
    const int tid = threadIdx.x;

    // ---- one-time staging ----
    for (int idx = tid; idx < 65 * 64; idx += 768) {
        int k = idx >> 6, f = idx & 63;
        sm.egw1t[f][k] = egw1[idx];
    }
    for (int idx = tid; idx < 128 * 192; idx += 768) {
        int o = idx / 192, r = idx % 192;
        sm.wpt[o][r] = g_Wpt[idx];
    }
    if (tid < 64) {
        sm.w65[tid] = ngw1[64 * 64 + tid];
        sm.bng1[tid] = ngb1[tid];
        sm.beg1[tid] = egb1[tid];
    } else if (tid < 192) {
        sm.b1p[tid - 64] = g_b1p[tid - 64];
    } else if (tid < 320) {
        sm.q[tid - 192] = g_q[tid - 192];
    } else if (tid == 320) {
        sm.qb = g_qb[0];
    }
    __syncthreads();

    const int f = tid & 63;
    const int row = tid >> 6;        // 0..11
    const int lane = tid & 31;
    const int half = (tid >> 5) & 1; // warp within row
    const float qbh = 0.5f * sm.qb;
    const int stride = gridDim.x * (12 * EPR);

    for (int base = blockIdx.x * (12 * EPR) + row * EPR; base < E; base += stride) {
        // ---- S0: row stages its own 6 edges ----
        if (f < EPR) {
            int e = base + f;
            int ok = (e < E);
            sm.valid[row][f] = ok;
            if (ok) {
                int r = ei[e], c = ei[E + e];
                sm.eRow[row][f] = r;
                sm.eCol[row][f] = c;
                float vx = v[r * 3 + 0], vy = v[r * 3 + 1], vz = v[r * 3 + 2];
                float wx = v[c * 3 + 0], wy = v[c * 3 + 1], wz = v[c * 3 + 2];
                float ux = evu[e * 3 + 0], uy = evu[e * 3 + 1], uz = evu[e * 3 + 2];
                sm.evu_s[row][f][0] = ux; sm.evu_s[row][f][1] = uy; sm.evu_s[row][f][2] = uz;
                sm.resI[row][f] = 1.0f - (vx * ux + vy * uy + vz * uz);
                sm.resJ[row][f] = 1.0f + (wx * ux + wy * uy + wz * uz);
                float cx = vy * wz - vz * wy;
                float cy = vz * wx - vx * wz;
                float cz = vx * wy - vy * wx;
                sm.EA[row][f][64] = sqrtf(cx * cx + cy * cy + cz * cz);
            } else {
                sm.eRow[row][f] = 0; sm.eCol[row][f] = 0;
                sm.resI[row][f] = 0.0f; sm.resJ[row][f] = 0.0f;
                sm.EA[row][f][64] = 0.0f;
                sm.evu_s[row][f][0] = sm.evu_s[row][f][1] = sm.evu_s[row][f][2] = 0.0f;
            }
        }
        for (int idx = f; idx < EPR * 16; idx += 64) {
            int j = idx >> 4, q4 = idx & 15;
            int e = base + j;
            float4 val = make_float4(0.f, 0.f, 0.f, 0.f);
            if (e < E) val = *(const float4*)&ea[e * 64 + q4 * 4];
            *(float4*)&sm.EA[row][j][q4 * 4] = val;
        }
        barrow(row);

        // ---- S1: h_e, h_i, h_j -> X[row] ----
        float pi[EPR], pj[EPR];
#pragma unroll
        for (int j = 0; j < EPR; j++) {
            pi[j] = 0.0f; pj[j] = 0.0f;
            if (sm.valid[row][j]) {
                pi[j] = g_P[sm.eRow[row][j] * 64 + f];
                pj[j] = g_P[sm.eCol[row][j] * 64 + f];
            }
        }
        {
            float a[EPR];
            float b0 = sm.beg1[f];
#pragma unroll
            for (int j = 0; j < EPR; j++) a[j] = b0;
#pragma unroll 4
            for (int k = 0; k < 64; k += 4) {
                float4 w = *(const float4*)&sm.egw1t[f][k];
#pragma unroll
                for (int j = 0; j < EPR; j++) {
                    float4 x = *(const float4*)&sm.EA[row][j][k];
                    a[j] += w.x * x.x + w.y * x.y + w.z * x.z + w.w * x.w;
                }
            }
            float w64v = sm.egw1t[f][64];
#pragma unroll
            for (int j = 0; j < EPR; j++) {
                a[j] += sm.EA[row][j][64] * w64v;
                sm.X[row][j][128 + f] = siluf(a[j]);
            }
        }
        {
            float w65v = sm.w65[f], b1v = sm.bng1[f];
#pragma unroll
            for (int j = 0; j < EPR; j++) {
                sm.X[row][j][f]      = siluf(pi[j] + sm.resI[row][j] * w65v + b1v);
                sm.X[row][j][64 + f] = siluf(pj[j] + sm.resJ[row][j] * w65v + b1v);
            }
        }
        barrow(row);

        // ---- S2: hm = X @ W' + b1p ; g = silu(hm) ; RED g_z ; coeff ----
        {
            float hA[EPR], hB[EPR];
            float bA = sm.b1p[f], bB = sm.b1p[64 + f];
#pragma unroll
            for (int j = 0; j < EPR; j++) { hA[j] = bA; hB[j] = bB; }
#pragma unroll 4
            for (int k = 0; k < 192; k += 4) {
                float4 wa = *(const float4*)&sm.wpt[f][k];
                float4 wb = *(const float4*)&sm.wpt[64 + f][k];
#pragma unroll
                for (int j = 0; j < EPR; j++) {
                    float4 x = *(const float4*)&sm.X[row][j][k];
                    hA[j] += wa.x * x.x + wa.y * x.y + wa.z * x.z + wa.w * x.w;
                    hB[j] += wb.x * x.x + wb.y * x.y + wb.z * x.z + wb.w * x.w;
                }
            }
            float qf = sm.q[f], qg = sm.q[64 + f];
            float p[EPR];
#pragma unroll
            for (int j = 0; j < EPR; j++) {
                float gA = siluf(hA[j]);
                float gB = siluf(hB[j]);
                if (sm.valid[row][j]) {
                    int dst = sm.eRow[row][j];
                    reds(&g_z[dst * 128 + f], gA);
                    reds(&g_z[dst * 128 + 64 + f], gB);
                }
                p[j] = gA * qf + gB * qg;
            }
            // butterfly reduce each p[j] within the warp (all lanes end with sum)
#pragma unroll
            for (int j = 0; j < EPR; j++) {
#pragma unroll
                for (int off = 16; off > 0; off >>= 1)
                    p[j] += __shfl_xor_sync(0xffffffffu, p[j], off);
            }
            // each warp REDs its half of the coefficient (qb split across halves)
            if (lane < 3 * EPR) {
                int j = lane / 3, c = lane % 3;
                if (sm.valid[row][j]) {
                    float cf = qbh + p[j];
                    reds(&g_vagg[sm.eRow[row][j] * 3 + c], sm.evu_s[row][j][c] * cf);
                }
            }
            if (half == 0 && lane < EPR && sm.valid[row][lane])
                reds(&g_deg[sm.eRow[row][lane]], 1.0f);
        }
        barrow(row);  // protect EA/X/scalars before next tile's S0
    }
}

// ---------------------------------------------------------------- node finalize
__global__ __launch_bounds__(256) void post_kernel(
    const float* __restrict__ s, const float* __restrict__ v,
    const float* __restrict__ mgw2, const float* __restrict__ mgb2,
    const float* __restrict__ upw, const float* __restrict__ upb,
    const float* __restrict__ lng, const float* __restrict__ lnb,
    float* __restrict__ outs, float* __restrict__ outv, int N) {
    __shared__ float mw2t[64][132];  // [f][k] = mgw2[k*64+f]
    __shared__ float upwt[64][68];
    __shared__ float zs[4][132];
    __shared__ float xs[4][68];
    __shared__ float sn[4][68];
    const int tid = threadIdx.x;
    for (int idx = tid; idx < 128 * 64; idx += 256) {
        int k = idx >> 6, f = idx & 63;
        mw2t[f][k] = mgw2[idx];
    }
    for (int idx = tid; idx < 64 * 64; idx += 256) {
        int k = idx >> 6, f = idx & 63;
        upwt[f][k] = upw[idx];
    }
    __syncthreads();
    const int slot = tid >> 6, f = tid & 63;
    for (int n0 = blockIdx.x * 4; n0 < N; n0 += gridDim.x * 4) {
        int n = n0 + slot;
        bool ok = (n < N);
        zs[slot][f]      = ok ? g_z[n * 128 + f] : 0.0f;
        zs[slot][64 + f] = ok ? g_z[n * 128 + 64 + f] : 0.0f;
        __syncthreads();
        float degv = ok ? g_deg[n] : 0.0f;
        float acc = degv * mgb2[f];
#pragma unroll 4
        for (int k = 0; k < 128; k += 4) {
            float4 w = *(const float4*)&mw2t[f][k];
            float4 x = *(const float4*)&zs[slot][k];
            acc += w.x * x.x + w.y * x.y + w.z * x.z + w.w * x.w;
        }
        xs[slot][f] = siluf(acc);
        __syncthreads();
        float acc2 = upb[f];
#pragma unroll 4
        for (int k = 0; k < 64; k += 4) {
            float4 w = *(const float4*)&upwt[f][k];
            float4 x = *(const float4*)&xs[slot][k];
            acc2 += w.x * x.x + w.y * x.y + w.z * x.z + w.w * x.w;
        }
        float snew = ok ? (s[n * 64 + f] + acc2) : 0.0f;
        sn[slot][f] = snew;
        __syncthreads();
        float sum = 0.0f, sq = 0.0f;
#pragma unroll 4
        for (int k = 0; k < 64; k += 4) {
            float4 t = *(const float4*)&sn[slot][k];
            sum += t.x + t.y + t.z + t.w;
            sq += t.x * t.x + t.y * t.y + t.z * t.z + t.w * t.w;
        }
        float mu = sum * (1.0f / 64.0f);
        float var = sq * (1.0f / 64.0f) - mu * mu;
        if (ok) {
            outs[n * 64 + f] = (snew - mu) * rsqrtf(var + 1e-5f) * lng[f] + lnb[f];
            if (f < 3) {
                float v0 = v[n * 3 + 0] + g_vagg[n * 3 + 0];
                float v1 = v[n * 3 + 1] + g_vagg[n * 3 + 1];
                float v2 = v[n * 3 + 2] + g_vagg[n * 3 + 2];
                float nrm = sqrtf(v0 * v0 + v1 * v1 + v2 * v2);
                float inv = 1.0f / fmaxf(nrm, 1e-6f);
                float val = (f == 0) ? v0 : (f == 1) ? v1 : v2;
                outv[n * 3 + f] = val * inv;
            }
        }
        __syncthreads();
    }
}

// ---------------------------------------------------------------- launch
extern "C" void kernel_launch(void* const* d_in, const int* in_sizes, int n_in,
                              void* d_out, int out_size) {
    const float* s    = (const float*)d_in[0];
    const float* v    = (const float*)d_in[1];
    const int*   ei   = (const int*)d_in[2];
    const float* ea   = (const float*)d_in[3];
    const float* evu  = (const float*)d_in[4];
    const float* ngw1 = (const float*)d_in[5];
    const float* ngb1 = (const float*)d_in[6];
    const float* ngw2 = (const float*)d_in[7];
    const float* ngb2 = (const float*)d_in[8];
    const float* egw1 = (const float*)d_in[9];
    const float* egb1 = (const float*)d_in[10];
    const float* egw2 = (const float*)d_in[11];
    const float* egb2 = (const float*)d_in[12];
    const float* mgw1 = (const float*)d_in[13];
    const float* mgb1 = (const float*)d_in[14];
    const float* mgw2 = (const float*)d_in[15];
    const float* mgb2 = (const float*)d_in[16];
    const float* pew  = (const float*)d_in[17];
    const float* peb  = (const float*)d_in[18];
    const float* upw  = (const float*)d_in[19];
    const float* upb  = (const float*)d_in[20];
    const float* lng  = (const float*)d_in[21];
    const float* lnb  = (const float*)d_in[22];

    const int N = in_sizes[0] / 64;
    const int E = in_sizes[2] / 2;

    float* outs = (float*)d_out;
    float* outv = outs + (size_t)N * 64;

    int nsm = 148;
    cudaDeviceGetAttribute(&nsm, cudaDevAttrMultiProcessorCount, 0);

    zero_kernel<<<512, 256>>>(N * 128, N * 3, N);
    pre_kernel<<<1184, 256>>>(s, ngw1, N);
    preW_kernel<<<128, 256>>>(ngw2, ngb2, egw2, egb2, mgw1, mgb1, mgw2, mgb2, pew, peb);

    cudaFuncSetAttribute(edge_kernel, cudaFuncAttributeMaxDynamicSharedMemorySize,
                         (int)sizeof(EdgeSmem));
    edge_kernel<<<nsm, 768, sizeof(EdgeSmem)>>>(
        v, ei, ea, evu, ngw1, ngb1, egw1, egb1, N, E);

    post_kernel<<<1184, 256>>>(s, v, mgw2, mgb2, upw, upb, lng, lnb, outs, outv, N);
}

// round 4
// speedup vs baseline: 2.9812x; 1.2164x over previous
#include <cuda_runtime.h>
#include <math.h>

#define MAXN 50000
#define MAXE 800000

// ---- device scratch (allocation-free rule) ----
__device__ float g_P[MAXN * 64];      // s @ ng_w1[0:64]
__device__ float g_z[MAXN * 128];     // segsum(silu(hm))
__device__ float g_vagg[MAXN * 3];
__device__ float g_deg[MAXN];
__device__ float g_Wpt[128 * 192];    // fused W' transposed: [o][r]
__device__ float g_b1p[128];          // fused bias into hm
__device__ float g_q[128];            // mg_w2 @ pe_w
__device__ float g_qb[1];             // b_mg2 @ pe_w + pe_b

__device__ __forceinline__ float siluf(float x) { return x / (1.0f + __expf(-x)); }

__device__ __forceinline__ void reds(float* p, float v) {
    asm volatile("red.global.add.f32 [%0], %1;" :: "l"(p), "f"(v) : "memory");
}
__device__ __forceinline__ void barrow(int id) {
    asm volatile("bar.sync %0, 64;" :: "r"(id) : "memory");
}

// ---- packed f32x2 helpers (Blackwell) ----
typedef unsigned long long u64t;
__device__ __forceinline__ u64t pack2(float x, float y) {
    u64t r; asm("mov.b64 %0, {%1,%2};" : "=l"(r) : "f"(x), "f"(y)); return r;
}
__device__ __forceinline__ float2 unpack2(u64t v) {
    float2 r; asm("mov.b64 {%0,%1}, %2;" : "=f"(r.x), "=f"(r.y) : "l"(v)); return r;
}
__device__ __forceinline__ void ffma2(u64t& d, u64t a, u64t b) {
    asm("fma.rn.f32x2 %0, %1, %2, %0;" : "+l"(d) : "l"(a), "l"(b));
}

// ---------------------------------------------------------------- zero scratch
__global__ void zero_kernel(int n128, int n3, int n1) {
    int i = blockIdx.x * blockDim.x + threadIdx.x;
    int stride = gridDim.x * blockDim.x;
    for (int k = i; k < n128; k += stride) g_z[k] = 0.0f;
    for (int k = i; k < n3; k += stride) g_vagg[k] = 0.0f;
    for (int k = i; k < n1; k += stride) g_deg[k] = 0.0f;
}

// ---------------------------------------------------------------- P = s @ ng_w1[0:64,:]
__global__ __launch_bounds__(256) void pre_kernel(const float* __restrict__ s,
                                                  const float* __restrict__ ngw1, int N) {
    __shared__ float wt[64][68];
    __shared__ float xs[4][68];
    const int tid = threadIdx.x;
    for (int idx = tid; idx < 64 * 64; idx += 256) {
        int k = idx >> 6, f = idx & 63;
        wt[f][k] = ngw1[idx];
    }
    __syncthreads();
    const int slot = tid >> 6, f = tid & 63;
    for (int n0 = blockIdx.x * 4; n0 < N; n0 += gridDim.x * 4) {
        int n = n0 + slot;
        xs[slot][f] = (n < N) ? s[n * 64 + f] : 0.0f;
        __syncthreads();
        float acc = 0.0f;
#pragma unroll 4
        for (int k = 0; k < 64; k += 4) {
            float4 w = *(const float4*)&wt[f][k];
            float4 x = *(const float4*)&xs[slot][k];
            acc += w.x * x.x + w.y * x.y + w.z * x.z + w.w * x.w;
        }
        if (n < N) g_P[n * 64 + f] = acc;
        __syncthreads();
    }
}

// ---------------------------------------------------------------- fold weights
__global__ void preW_kernel(const float* __restrict__ ngw2, const float* __restrict__ ngb2,
                            const float* __restrict__ egw2, const float* __restrict__ egb2,
                            const float* __restrict__ mgw1, const float* __restrict__ mgb1,
                            const float* __restrict__ mgw2, const float* __restrict__ mgb2,
                            const float* __restrict__ pew, const float* __restrict__ peb) {
    int idx = blockIdx.x * blockDim.x + threadIdx.x;
    int stride = gridDim.x * blockDim.x;
    for (int t = idx; t < 128 * 192 + 128 + 128 + 1; t += stride) {
        if (t < 128 * 192) {
            int o = t / 192, r = t % 192;
            int seg = r >> 6, rr = r & 63, koff = seg * 64;
            const float* src = (seg < 2) ? ngw2 : egw2;
            float val = 0.0f;
            for (int k = 0; k < 64; k++)
                val += src[rr * 64 + k] * mgw1[(koff + k) * 128 + o];
            g_Wpt[o * 192 + r] = val;
        } else if (t < 128 * 192 + 128) {
            int o = t - 128 * 192;
            float val = mgb1[o];
            for (int k = 0; k < 64; k++) {
                val += ngb2[k] * (mgw1[k * 128 + o] + mgw1[(64 + k) * 128 + o]);
                val += egb2[k] * mgw1[(128 + k) * 128 + o];
            }
            g_b1p[o] = val;
        } else if (t < 128 * 192 + 256) {
            int o = t - 128 * 192 - 128;
            float val = 0.0f;
            for (int j = 0; j < 64; j++) val += mgw2[o * 64 + j] * pew[j];
            g_q[o] = val;
        } else {
            float val = peb[0];
            for (int j = 0; j < 64; j++) val += mgb2[j] * pew[j];
            g_qb[0] = val;
        }
    }
}

// ---------------------------------------------------------------- fused edge kernel
// 768 threads = 12 independent rows x 64 lanes; each row owns 8 edges/tile as 4 pairs.
// Packed fp32 (fma.rn.f32x2): each f32x2 half carries one edge of the pair.
#define EPR 8   // edges per row
#define NPAIR 4

struct __align__(16) EdgeSmem {
    float egw1t[64][68];            // eg_w1 transposed [f][k], k=0..64
    float wpt[128][196];            // fused W' transposed [o][r]
    float XP[12][NPAIR][192][2];    // pair-interleaved X: [row][pair][k][edge-in-pair]
    float EAP[12][NPAIR][66][2];    // pair-interleaved edge_attr (+cross at k=64)
    float w65[64], bng1[64], beg1[64];
    float b1p[128], q[128];
    float resI[12][EPR], resJ[12][EPR];
    float evu_s[12][EPR][3];
    int eRow[12][EPR], eCol[12][EPR], valid[12][EPR];
    float qb;
};

__global__ __launch_bounds__(768) void edge_kernel(
    const float* __restrict__ v, const int* __restrict__ ei,
    const float* __restrict__ ea, const float* __restrict__ evu,
    const float* __restrict__ ngw1, const float* __restrict__ ngb1,
    const float* __restrict__ egw1, const float* __restrict__ egb1,
    int N, int E) {
    extern __shared__ char smem_raw[];
    EdgeSmem& sm = *reinterpret_cast<EdgeSmem*>(smem_raw);
    const int tid = threadIdx.x;

    // ---- one-time staging ----
    for (int idx = tid; idx < 65 * 64; idx += 768) {
        int k = idx >> 6, f = idx & 63;
        sm.egw1t[f][k] = egw1[idx];
    }
    for (int idx = tid; idx < 128 * 192; idx += 768) {
        int o = idx / 192, r = idx % 192;
        sm.wpt[o][r] = g_Wpt[idx];
    }
    if (tid < 64) {
        sm.w65[tid] = ngw1[64 * 64 + tid];
        sm.bng1[tid] = ngb1[tid];
        sm.beg1[tid] = egb1[tid];
    } else if (tid < 192) {
        sm.b1p[tid - 64] = g_b1p[tid - 64];
    } else if (tid < 320) {
        sm.q[tid - 192] = g_q[tid - 192];
    } else if (tid == 320) {
        sm.qb = g_qb[0];
    }
    __syncthreads();

    const int f = tid & 63;
    const int row = tid >> 6;        // 0..11
    const int lane = tid & 31;
    const int half = (tid >> 5) & 1;
    const float qbh = 0.5f * sm.qb;
    const int stride = gridDim.x * (12 * EPR);

    // hoisted per-lane constants / pointers
    const float begf = sm.beg1[f];
    const float w64v = sm.egw1t[f][64];
    const float w65v = sm.w65[f], b1v = sm.bng1[f];
    const float bA = sm.b1p[f], bB = sm.b1p[64 + f];
    const float qf = sm.q[f], qg = sm.q[64 + f];
    const float* egrow = sm.egw1t[f];
    const float* warow = sm.wpt[f];
    const float* wbrow = sm.wpt[64 + f];
    float (*XPr)[192][2] = sm.XP[row];
    float (*EAPr)[66][2] = sm.EAP[row];
    int* eRowR = sm.eRow[row];
    int* eColR = sm.eCol[row];
    int* validR = sm.valid[row];

    for (int base = blockIdx.x * (12 * EPR) + row * EPR; base < E; base += stride) {
        // ---- S0: stage 8 edges (scalars + pair-interleaved edge_attr) ----
        if (f < EPR) {
            int e = base + f;
            int ok = (e < E);
            validR[f] = ok;
            if (ok) {
                int r = ei[e], c = ei[E + e];
                eRowR[f] = r;
                eColR[f] = c;
                float vx = v[r * 3 + 0], vy = v[r * 3 + 1], vz = v[r * 3 + 2];
                float wx = v[c * 3 + 0], wy = v[c * 3 + 1], wz = v[c * 3 + 2];
                float ux = evu[e * 3 + 0], uy = evu[e * 3 + 1], uz = evu[e * 3 + 2];
                sm.evu_s[row][f][0] = ux; sm.evu_s[row][f][1] = uy; sm.evu_s[row][f][2] = uz;
                sm.resI[row][f] = 1.0f - (vx * ux + vy * uy + vz * uz);
                sm.resJ[row][f] = 1.0f + (wx * ux + wy * uy + wz * uz);
                float cx = vy * wz - vz * wy;
                float cy = vz * wx - vx * wz;
                float cz = vx * wy - vy * wx;
                EAPr[f >> 1][64][f & 1] = sqrtf(cx * cx + cy * cy + cz * cz);
            } else {
                eRowR[f] = 0; eColR[f] = 0;
                sm.resI[row][f] = 0.0f; sm.resJ[row][f] = 0.0f;
                EAPr[f >> 1][64][f & 1] = 0.0f;
                sm.evu_s[row][f][0] = sm.evu_s[row][f][1] = sm.evu_s[row][f][2] = 0.0f;
            }
        }
        for (int idx = f; idx < NPAIR * 32; idx += 64) {
            int p = idx >> 5, kk = (idx & 31) * 2;
            int e0 = base + 2 * p, e1 = e0 + 1;
            float2 a0 = make_float2(0.f, 0.f), a1 = a0;
            if (e0 < E) a0 = *(const float2*)&ea[(size_t)e0 * 64 + kk];
            if (e1 < E) a1 = *(const float2*)&ea[(size_t)e1 * 64 + kk];
            float4 w; w.x = a0.x; w.y = a1.x; w.z = a0.y; w.w = a1.y;
            *(float4*)&EAPr[p][kk][0] = w;
        }
        barrow(row);

        // ---- S1: h_e (packed GEMM), h_i/h_j via P ----
        {
            u64t aE[NPAIR];
            u64t binit = pack2(begf, begf);
#pragma unroll
            for (int p = 0; p < NPAIR; p++) aE[p] = binit;
#pragma unroll 4
            for (int k = 0; k < 64; k += 4) {
                float4 w = *(const float4*)&egrow[k];
                u64t w0 = pack2(w.x, w.x), w1 = pack2(w.y, w.y);
                u64t w2 = pack2(w.z, w.z), w3 = pack2(w.w, w.w);
#pragma unroll
                for (int p = 0; p < NPAIR; p++) {
                    ulonglong2 q0 = *(const ulonglong2*)&EAPr[p][k][0];
                    ulonglong2 q1 = *(const ulonglong2*)&EAPr[p][k + 2][0];
                    ffma2(aE[p], q0.x, w0);
                    ffma2(aE[p], q0.y, w1);
                    ffma2(aE[p], q1.x, w2);
                    ffma2(aE[p], q1.y, w3);
                }
            }
            u64t wc = pack2(w64v, w64v);
#pragma unroll
            for (int p = 0; p < NPAIR; p++) {
                u64t cr = *(const u64t*)&EAPr[p][64][0];
                ffma2(aE[p], cr, wc);
                float2 g = unpack2(aE[p]);
                float2 o; o.x = siluf(g.x); o.y = siluf(g.y);
                *(float2*)&XPr[p][128 + f][0] = o;
            }
        }
#pragma unroll
        for (int p = 0; p < NPAIR; p++) {
            int j0 = 2 * p, j1 = 2 * p + 1;
            float pi0 = 0.f, pi1 = 0.f, pj0 = 0.f, pj1 = 0.f;
            if (validR[j0]) { pi0 = g_P[eRowR[j0] * 64 + f]; pj0 = g_P[eColR[j0] * 64 + f]; }
            if (validR[j1]) { pi1 = g_P[eRowR[j1] * 64 + f]; pj1 = g_P[eColR[j1] * 64 + f]; }
            float2 hi, hj;
            hi.x = siluf(pi0 + sm.resI[row][j0] * w65v + b1v);
            hi.y = siluf(pi1 + sm.resI[row][j1] * w65v + b1v);
            hj.x = siluf(pj0 + sm.resJ[row][j0] * w65v + b1v);
            hj.y = siluf(pj1 + sm.resJ[row][j1] * w65v + b1v);
            *(float2*)&XPr[p][f][0] = hi;
            *(float2*)&XPr[p][64 + f][0] = hj;
        }
        barrow(row);

        // ---- S2: hm = X @ W' + b1p (packed) ; g = silu ; RED g_z ; coeff ----
        {
            u64t accA[NPAIR], accB[NPAIR];
            u64t ia = pack2(bA, bA), ib = pack2(bB, bB);
#pragma unroll
            for (int p = 0; p < NPAIR; p++) { accA[p] = ia; accB[p] = ib; }
#pragma unroll 4
            for (int k = 0; k < 192; k += 4) {
                float4 wa = *(const float4*)&warow[k];
                float4 wb = *(const float4*)&wbrow[k];
                u64t wa0 = pack2(wa.x, wa.x), wa1 = pack2(wa.y, wa.y);
                u64t wa2 = pack2(wa.z, wa.z), wa3 = pack2(wa.w, wa.w);
                u64t wb0 = pack2(wb.x, wb.x), wb1 = pack2(wb.y, wb.y);
                u64t wb2 = pack2(wb.z, wb.z), wb3 = pack2(wb.w, wb.w);
#pragma unroll
                for (int p = 0; p < NPAIR; p++) {
                    ulonglong2 q0 = *(const ulonglong2*)&XPr[p][k][0];
                    ulonglong2 q1 = *(const ulonglong2*)&XPr[p][k + 2][0];
                    ffma2(accA[p], q0.x, wa0);
                    ffma2(accB[p], q0.x, wb0);
                    ffma2(accA[p], q0.y, wa1);
                    ffma2(accB[p], q0.y, wb1);
                    ffma2(accA[p], q1.x, wa2);
                    ffma2(accB[p], q1.x, wb2);
                    ffma2(accA[p], q1.y, wa3);
                    ffma2(accB[p], q1.y, wb3);
                }
            }
            float pco[EPR];
#pragma unroll
            for (int p = 0; p < NPAIR; p++) {
                float2 gA = unpack2(accA[p]);
                float2 gB = unpack2(accB[p]);
                gA.x = siluf(gA.x); gA.y = siluf(gA.y);
                gB.x = siluf(gB.x); gB.y = siluf(gB.y);
                int j0 = 2 * p, j1 = 2 * p + 1;
                if (validR[j0]) {
                    int dst = eRowR[j0];
                    reds(&g_z[dst * 128 + f], gA.x);
                    reds(&g_z[dst * 128 + 64 + f], gB.x);
                }
                if (validR[j1]) {
                    int dst = eRowR[j1];
                    reds(&g_z[dst * 128 + f], gA.y);
                    reds(&g_z[dst * 128 + 64 + f], gB.y);
                }
                pco[j0] = gA.x * qf + gB.x * qg;
                pco[j1] = gA.y * qf + gB.y * qg;
            }
#pragma unroll
            for (int j = 0; j < EPR; j++) {
#pragma unroll
                for (int off = 16; off > 0; off >>= 1)
                    pco[j] += __shfl_xor_sync(0xffffffffu, pco[j], off);
            }
            if (lane < 3 * EPR) {
                int j = lane / 3, c = lane % 3;
                if (validR[j]) {
                    float cf = qbh + pco[j];
                    reds(&g_vagg[eRowR[j] * 3 + c], sm.evu_s[row][j][c] * cf);
                }
            }
            if (half == 0 && lane < EPR && validR[lane])
                reds(&g_deg[eRowR[lane]], 1.0f);
        }
        barrow(row);  // protect EAP/XP/scalars before next tile's S0
    }
}

// ---------------------------------------------------------------- node finalize
__global__ __launch_bounds__(256) void post_kernel(
    const float* __restrict__ s, const float* __restrict__ v,
    const float* __restrict__ mgw2, const float* __restrict__ mgb2,
    const float* __restrict__ upw, const float* __restrict__ upb,
    const float* __restrict__ lng, const float* __restrict__ lnb,
    float* __restrict__ outs, float* __restrict__ outv, int N) {
    __shared__ float mw2t[64][132];
    __shared__ float upwt[64][68];
    __shared__ float zs[4][132];
    __shared__ float xs[4][68];
    __shared__ float sn[4][68];
    const int tid = threadIdx.x;
    for (int idx = tid; idx < 128 * 64; idx += 256) {
        int k = idx >> 6, f = idx & 63;
        mw2t[f][k] = mgw2[idx];
    }
    for (int idx = tid; idx < 64 * 64; idx += 256) {
        int k = idx >> 6, f = idx & 63;
        upwt[f][k] = upw[idx];
    }
    __syncthreads();
    const int slot = tid >> 6, f = tid & 63;
    for (int n0 = blockIdx.x * 4; n0 < N; n0 += gridDim.x * 4) {
        int n = n0 + slot;
        bool ok = (n < N);
        zs[slot][f]      = ok ? g_z[n * 128 + f] : 0.0f;
        zs[slot][64 + f] = ok ? g_z[n * 128 + 64 + f] : 0.0f;
        __syncthreads();
        float degv = ok ? g_deg[n] : 0.0f;
        float acc = degv * mgb2[f];
#pragma unroll 4
        for (int k = 0; k < 128; k += 4) {
            float4 w = *(const float4*)&mw2t[f][k];
            float4 x = *(const float4*)&zs[slot][k];
            acc += w.x * x.x + w.y * x.y + w.z * x.z + w.w * x.w;
        }
        xs[slot][f] = siluf(acc);
        __syncthreads();
        float acc2 = upb[f];
#pragma unroll 4
        for (int k = 0; k < 64; k += 4) {
            float4 w = *(const float4*)&upwt[f][k];
            float4 x = *(const float4*)&xs[slot][k];
            acc2 += w.x * x.x + w.y * x.y + w.z * x.z + w.w * x.w;
        }
        float snew = ok ? (s[n * 64 + f] + acc2) : 0.0f;
        sn[slot][f] = snew;
        __syncthreads();
        float sum = 0.0f, sq = 0.0f;
#pragma unroll 4
        for (int k = 0; k < 64; k += 4) {
            float4 t = *(const float4*)&sn[slot][k];
            sum += t.x + t.y + t.z + t.w;
            sq += t.x * t.x + t.y * t.y + t.z * t.z + t.w * t.w;
        }
        float mu = sum * (1.0f / 64.0f);
        float var = sq * (1.0f / 64.0f) - mu * mu;
        if (ok) {
            outs[n * 64 + f] = (snew - mu) * rsqrtf(var + 1e-5f) * lng[f] + lnb[f];
            if (f < 3) {
                float v0 = v[n * 3 + 0] + g_vagg[n * 3 + 0];
                float v1 = v[n * 3 + 1] + g_vagg[n * 3 + 1];
                float v2 = v[n * 3 + 2] + g_vagg[n * 3 + 2];
                float nrm = sqrtf(v0 * v0 + v1 * v1 + v2 * v2);
                float inv = 1.0f / fmaxf(nrm, 1e-6f);
                float val = (f == 0) ? v0 : (f == 1) ? v1 : v2;
                outv[n * 3 + f] = val * inv;
            }
        }
        __syncthreads();
    }
}

// ---------------------------------------------------------------- launch
extern "C" void kernel_launch(void* const* d_in, const int* in_sizes, int n_in,
                              void* d_out, int out_size) {
    const float* s    = (const float*)d_in[0];
    const float* v    = (const float*)d_in[1];
    const int*   ei   = (const int*)d_in[2];
    const float* ea   = (const float*)d_in[3];
    const float* evu  = (const float*)d_in[4];
    const float* ngw1 = (const float*)d_in[5];
    const float* ngb1 = (const float*)d_in[6];
    const float* ngw2 = (const float*)d_in[7];
    const float* ngb2 = (const float*)d_in[8];
    const float* egw1 = (const float*)d_in[9];
    const float* egb1 = (const float*)d_in[10];
    const float* egw2 = (const float*)d_in[11];
    const float* egb2 = (const float*)d_in[12];
    const float* mgw1 = (const float*)d_in[13];
    const float* mgb1 = (const float*)d_in[14];
    const float* mgw2 = (const float*)d_in[15];
    const float* mgb2 = (const float*)d_in[16];
    const float* pew  = (const float*)d_in[17];
    const float* peb  = (const float*)d_in[18];
    const float* upw  = (const float*)d_in[19];
    const float* upb  = (const float*)d_in[20];
    const float* lng  = (const float*)d_in[21];
    const float* lnb  = (const float*)d_in[22];

    const int N = in_sizes[0] / 64;
    const int E = in_sizes[2] / 2;

    float* outs = (float*)d_out;
    float* outv = outs + (size_t)N * 64;

    int nsm = 148;
    cudaDeviceGetAttribute(&nsm, cudaDevAttrMultiProcessorCount, 0);

    zero_kernel<<<512, 256>>>(N * 128, N * 3, N);
    pre_kernel<<<1184, 256>>>(s, ngw1, N);
    preW_kernel<<<128, 256>>>(ngw2, ngb2, egw2, egb2, mgw1, mgb1, mgw2, mgb2, pew, peb);

    cudaFuncSetAttribute(edge_kernel, cudaFuncAttributeMaxDynamicSharedMemorySize,
                         (int)sizeof(EdgeSmem));
    edge_kernel<<<nsm, 768, sizeof(EdgeSmem)>>>(
        v, ei, ea, evu, ngw1, ngb1, egw1, egb1, N, E);

    post_kernel<<<1184, 256>>>(s, v, mgw2, mgb2, upw, upb, lng, lnb, outs, outv, N);
}